// round 13
// baseline (speedup 1.0000x reference)
#include <cuda_runtime.h>
#include <math.h>

// ---------------- problem constants ----------------
#define DIMV   1152
#define HEADSV 16
#define HD     72
#define HD1    73
#define HIDV   4608
#define HID2   9216      // 2*HID
#define BBATCH 2
#define NSEQ   4096
#define MT     8192      // BBATCH*NSEQ
#define NCHUNK 16
#define KV_CELLS (HD*HD1)   // 5256
#define CPT    21           // ceil(5256/256)

// ---------------- scratch (device globals; no allocs) ----------------
__device__ float g_mods[BBATCH*6*DIMV];
__device__ float g_x  [(size_t)MT*DIMV];   // modulated input / reused as attn output
__device__ float g_q  [(size_t)MT*DIMV];
__device__ float g_k  [(size_t)MT*DIMV];
__device__ float g_v  [(size_t)MT*DIMV];
__device__ float g_kvp[(size_t)BBATCH*HEADSV*NCHUNK*KV_CELLS];
__device__ float g_kv [(size_t)BBATCH*HEADSV*KV_CELLS];
__device__ float g_h2 [(size_t)MT*DIMV];
__device__ float g_y  [(size_t)MT*HID2];
__device__ float g_y2 [(size_t)MT*HIDV];

// ---------------- small helpers ----------------
template<int ACT>
__device__ __forceinline__ float activate(float v) {
    if (ACT == 1) return fmaxf(v, 0.f);
    if (ACT == 2) return v / (1.f + expf(-v));
    return v;
}

// ---------------- mods = scale_shift_table + temb ----------------
__global__ void mods_kernel(const float* __restrict__ temb,
                            const float* __restrict__ sst) {
    int i = blockIdx.x * 256 + threadIdx.x;
    if (i < BBATCH * 6 * DIMV)
        g_mods[i] = sst[i % (6 * DIMV)] + temb[i];
}

// ---------------- RMSNorm + adaLN modulation (float4) ----------------
__global__ void __launch_bounds__(256) rms_mod_kernel(
    const float* __restrict__ h, float* __restrict__ out,
    int shift_sel, int scale_sel)
{
    int row = blockIdx.x;              // 0..MT-1
    int b   = row >> 12;               // /NSEQ
    const float4* hr4 = (const float4*)(h + (size_t)row * DIMV);
    __shared__ float red[256];
    float s = 0.f;
    for (int i = threadIdx.x; i < DIMV / 4; i += 256) {
        float4 v = hr4[i];
        s += v.x * v.x + v.y * v.y + v.z * v.z + v.w * v.w;
    }
    red[threadIdx.x] = s;
    __syncthreads();
    for (int off = 128; off; off >>= 1) {
        if (threadIdx.x < off) red[threadIdx.x] += red[threadIdx.x + off];
        __syncthreads();
    }
    float inv = rsqrtf(red[0] / (float)DIMV + 1e-6f);
    const float4* sh4 = (const float4*)(g_mods + (b * 6 + shift_sel) * DIMV);
    const float4* sc4 = (const float4*)(g_mods + (b * 6 + scale_sel) * DIMV);
    float4* orow4 = (float4*)(out + (size_t)row * DIMV);
    for (int i = threadIdx.x; i < DIMV / 4; i += 256) {
        float4 v = hr4[i], sc = sc4[i], sh = sh4[i], o;
        o.x = v.x * inv * (1.f + sc.x) + sh.x;
        o.y = v.y * inv * (1.f + sc.y) + sh.y;
        o.z = v.z * inv * (1.f + sc.z) + sh.z;
        o.w = v.w * inv * (1.f + sc.w) + sh.w;
        orow4[i] = o;
    }
}

// ---------------- generic fp32 GEMM: C = epi(A[M,K] @ W[Nt,K]^T) ----------------
// Double-buffered smem + register prefetch: one __syncthreads per k-iteration.
// Vectorized (float4) epilogue.
// ACT: 0 none, 1 relu, 2 silu
// EPI: 0 act(acc+bias); 1 gate*(acc+bias)+resid; 2 resid+gate*acc
template<int ACT, int EPI>
__global__ void __launch_bounds__(256, 2) gemm_kernel(
    const float* __restrict__ A, const float* __restrict__ W,
    const float* __restrict__ bias, float* __restrict__ C,
    int K, int Nt,
    const float* __restrict__ resid, const float* __restrict__ gates,
    int gate_sel)
{
    __shared__ float As[2][16][132];
    __shared__ float Bs[2][16][132];
    const int bm = blockIdx.y * 128;
    const int bn = blockIdx.x * 128;
    const int tid = threadIdx.x;
    const int lr = tid >> 2;             // 0..63
    const int lc = (tid & 3) << 2;       // 0,4,8,12
    const int tx = tid & 15, ty = tid >> 4;

    const float* Ap = A + (size_t)(bm + lr) * K + lc;
    const float* Wp = W + (size_t)(bn + lr) * K + lc;
    const size_t str64 = (size_t)64 * K;

    float acc[8][8];
#pragma unroll
    for (int i = 0; i < 8; i++)
#pragma unroll
        for (int j = 0; j < 8; j++) acc[i][j] = 0.f;

    // prologue: load tile 0 into registers
    float4 a0 = *(const float4*)(Ap);
    float4 a1 = *(const float4*)(Ap + str64);
    float4 b0 = *(const float4*)(Wp);
    float4 b1 = *(const float4*)(Wp + str64);

    int s = 0;
    for (int k0 = 0; k0 < K; k0 += 16, s ^= 1) {
        As[s][lc+0][lr] = a0.x; As[s][lc+1][lr] = a0.y; As[s][lc+2][lr] = a0.z; As[s][lc+3][lr] = a0.w;
        As[s][lc+0][lr+64] = a1.x; As[s][lc+1][lr+64] = a1.y; As[s][lc+2][lr+64] = a1.z; As[s][lc+3][lr+64] = a1.w;
        Bs[s][lc+0][lr] = b0.x; Bs[s][lc+1][lr] = b0.y; Bs[s][lc+2][lr] = b0.z; Bs[s][lc+3][lr] = b0.w;
        Bs[s][lc+0][lr+64] = b1.x; Bs[s][lc+1][lr+64] = b1.y; Bs[s][lc+2][lr+64] = b1.z; Bs[s][lc+3][lr+64] = b1.w;
        __syncthreads();   // stage s fully written; prior reads of s finished 2 iters ago

        int kn = k0 + 16;
        if (kn < K) {
            a0 = *(const float4*)(Ap + kn);
            a1 = *(const float4*)(Ap + str64 + kn);
            b0 = *(const float4*)(Wp + kn);
            b1 = *(const float4*)(Wp + str64 + kn);
        }

#pragma unroll
        for (int kk = 0; kk < 16; kk++) {
            float ar[8], br[8];
            *(float4*)(ar)     = *(const float4*)(&As[s][kk][ty*8]);
            *(float4*)(ar + 4) = *(const float4*)(&As[s][kk][ty*8 + 4]);
            *(float4*)(br)     = *(const float4*)(&Bs[s][kk][tx*8]);
            *(float4*)(br + 4) = *(const float4*)(&Bs[s][kk][tx*8 + 4]);
#pragma unroll
            for (int i = 0; i < 8; i++)
#pragma unroll
                for (int j = 0; j < 8; j++)
                    acc[i][j] = fmaf(ar[i], br[j], acc[i][j]);
        }
    }

    // vectorized epilogue: two float4 per row-slice
#pragma unroll
    for (int i = 0; i < 8; i++) {
        int row  = bm + ty * 8 + i;
        int bidx = row >> 12;            // row / NSEQ
        float* crow = C + (size_t)row * Nt + bn;
        const float* grow = (EPI != 0) ? (gates + (bidx * 6 + gate_sel) * DIMV + bn) : (const float*)0;
        const float* rrow = (EPI != 0) ? (resid + (size_t)row * Nt + bn) : (const float*)0;
#pragma unroll
        for (int j4 = 0; j4 < 2; j4++) {
            int col = tx * 8 + j4 * 4;
            float4 v = *(const float4*)(&acc[i][j4 * 4]);
            if (EPI == 0) {
                if (bias) {
                    float4 bv = *(const float4*)(bias + bn + col);
                    v.x += bv.x; v.y += bv.y; v.z += bv.z; v.w += bv.w;
                }
                v.x = activate<ACT>(v.x); v.y = activate<ACT>(v.y);
                v.z = activate<ACT>(v.z); v.w = activate<ACT>(v.w);
            } else if (EPI == 1) {
                float4 bv = *(const float4*)(bias + bn + col);
                float4 gv = *(const float4*)(grow + col);
                float4 rv = *(const float4*)(rrow + col);
                v.x = gv.x * (v.x + bv.x) + rv.x;
                v.y = gv.y * (v.y + bv.y) + rv.y;
                v.z = gv.z * (v.z + bv.z) + rv.z;
                v.w = gv.w * (v.w + bv.w) + rv.w;
            } else {
                float4 gv = *(const float4*)(grow + col);
                float4 rv = *(const float4*)(rrow + col);
                v.x = rv.x + gv.x * v.x;
                v.y = rv.y + gv.y * v.y;
                v.z = rv.z + gv.z * v.z;
                v.w = rv.w + gv.w * v.w;
            }
            *(float4*)(crow + col) = v;
        }
    }
}

// ---------------- fused QKV GEMM (double-buffered, vectorized epilogue) --------
__global__ void __launch_bounds__(256, 2) gemm_qkv_kernel(
    const float* __restrict__ A,
    const float* __restrict__ Wq, const float* __restrict__ bq,
    const float* __restrict__ Wk, const float* __restrict__ bk,
    const float* __restrict__ Wv, const float* __restrict__ bv,
    float* __restrict__ Cq, float* __restrict__ Ck, float* __restrict__ Cv)
{
    const int K = DIMV;
    __shared__ float As[2][16][132];
    __shared__ float Bs[2][16][132];
    const int bm = blockIdx.y * 128;
    const int bng = blockIdx.x * 128;          // global column in [0, 3*DIMV)
    const int which = bng / DIMV;              // 0=q, 1=k, 2=v (block-uniform)
    const int bn = bng - which * DIMV;         // local column in [0, DIMV)
    const float* W    = (which == 0) ? Wq : (which == 1) ? Wk : Wv;
    const float* bias = (which == 0) ? bq : (which == 1) ? bk : bv;
    float* C          = (which == 0) ? Cq : (which == 1) ? Ck : Cv;
    const bool relu   = (which < 2);

    const int tid = threadIdx.x;
    const int lr = tid >> 2;
    const int lc = (tid & 3) << 2;
    const int tx = tid & 15, ty = tid >> 4;

    const float* Ap = A + (size_t)(bm + lr) * K + lc;
    const float* Wp = W + (size_t)(bn + lr) * K + lc;
    const size_t str64 = (size_t)64 * K;

    float acc[8][8];
#pragma unroll
    for (int i = 0; i < 8; i++)
#pragma unroll
        for (int j = 0; j < 8; j++) acc[i][j] = 0.f;

    float4 a0 = *(const float4*)(Ap);
    float4 a1 = *(const float4*)(Ap + str64);
    float4 b0 = *(const float4*)(Wp);
    float4 b1 = *(const float4*)(Wp + str64);

    int s = 0;
    for (int k0 = 0; k0 < K; k0 += 16, s ^= 1) {
        As[s][lc+0][lr] = a0.x; As[s][lc+1][lr] = a0.y; As[s][lc+2][lr] = a0.z; As[s][lc+3][lr] = a0.w;
        As[s][lc+0][lr+64] = a1.x; As[s][lc+1][lr+64] = a1.y; As[s][lc+2][lr+64] = a1.z; As[s][lc+3][lr+64] = a1.w;
        Bs[s][lc+0][lr] = b0.x; Bs[s][lc+1][lr] = b0.y; Bs[s][lc+2][lr] = b0.z; Bs[s][lc+3][lr] = b0.w;
        Bs[s][lc+0][lr+64] = b1.x; Bs[s][lc+1][lr+64] = b1.y; Bs[s][lc+2][lr+64] = b1.z; Bs[s][lc+3][lr+64] = b1.w;
        __syncthreads();

        int kn = k0 + 16;
        if (kn < K) {
            a0 = *(const float4*)(Ap + kn);
            a1 = *(const float4*)(Ap + str64 + kn);
            b0 = *(const float4*)(Wp + kn);
            b1 = *(const float4*)(Wp + str64 + kn);
        }

#pragma unroll
        for (int kk = 0; kk < 16; kk++) {
            float ar[8], br[8];
            *(float4*)(ar)     = *(const float4*)(&As[s][kk][ty*8]);
            *(float4*)(ar + 4) = *(const float4*)(&As[s][kk][ty*8 + 4]);
            *(float4*)(br)     = *(const float4*)(&Bs[s][kk][tx*8]);
            *(float4*)(br + 4) = *(const float4*)(&Bs[s][kk][tx*8 + 4]);
#pragma unroll
            for (int i = 0; i < 8; i++)
#pragma unroll
                for (int j = 0; j < 8; j++)
                    acc[i][j] = fmaf(ar[i], br[j], acc[i][j]);
        }
    }

#pragma unroll
    for (int i = 0; i < 8; i++) {
        int row = bm + ty * 8 + i;
        float* crow = C + (size_t)row * DIMV + bn;
#pragma unroll
        for (int j4 = 0; j4 < 2; j4++) {
            int col = tx * 8 + j4 * 4;
            float4 v = *(const float4*)(&acc[i][j4 * 4]);
            float4 bv = *(const float4*)(bias + bn + col);
            v.x += bv.x; v.y += bv.y; v.z += bv.z; v.w += bv.w;
            if (relu) {
                v.x = fmaxf(v.x, 0.f); v.y = fmaxf(v.y, 0.f);
                v.z = fmaxf(v.z, 0.f); v.w = fmaxf(v.w, 0.f);
            }
            *(float4*)(crow + col) = v;
        }
    }
}

// ---------------- linear attention: partial kv = sum_n k ⊗ [v;1] ----------------
// d/e cell coordinates advance incrementally (256 = 3*73 + 37), replacing the
// per-iteration integer divisions.
__global__ void __launch_bounds__(256) kv_partial_kernel() {
    int bh    = blockIdx.x;              // 0..B*H-1
    int chunk = blockIdx.y;              // 0..NCHUNK-1
    int b = bh / HEADSV, h = bh % HEADSV;
    int n0 = chunk * (NSEQ / NCHUNK);    // 256 rows per chunk
    __shared__ float sk[16][HD];
    __shared__ float sv[16][HD1];
    int tid = threadIdx.x;
    float acc[CPT];
#pragma unroll
    for (int i = 0; i < CPT; i++) acc[i] = 0.f;

    const int d0 = tid / HD1;
    const int e0 = tid - d0 * HD1;

    for (int nt = 0; nt < NSEQ / NCHUNK; nt += 16) {
        __syncthreads();
        for (int idx = tid; idx < 16 * HD; idx += 256) {
            int ns = idx / HD, d = idx % HD;
            size_t r = (size_t)(b * NSEQ + n0 + nt + ns) * DIMV + h * HD + d;
            sk[ns][d] = g_k[r];
            sv[ns][d] = g_v[r];
        }
        if (tid < 16) sv[tid][HD] = 1.0f;
        __syncthreads();
        int d = d0, e = e0, c = tid;
#pragma unroll
        for (int i = 0; i < CPT; i++) {
            if (c < KV_CELLS) {
#pragma unroll
                for (int ns = 0; ns < 16; ns++)
                    acc[i] = fmaf(sk[ns][d], sv[ns][e], acc[i]);
            }
            c += 256; d += 3; e += 37;
            if (e >= HD1) { e -= HD1; d += 1; }
        }
    }
    float* outp = g_kvp + ((size_t)bh * NCHUNK + chunk) * KV_CELLS;
#pragma unroll
    for (int i = 0; i < CPT; i++) {
        int c = tid + i * 256;
        if (c < KV_CELLS) outp[c] = acc[i];
    }
}

__global__ void kv_reduce_kernel() {
    int bh = blockIdx.x;
    for (int c = threadIdx.x; c < KV_CELLS; c += 256) {
        float s = 0.f;
        for (int j = 0; j < NCHUNK; j++)
            s += g_kvp[((size_t)bh * NCHUNK + j) * KV_CELLS + c];
        g_kv[(size_t)bh * KV_CELLS + c] = s;
    }
}

// ---------------- out = (q @ kv)[:72] / ((q @ kv)[72]+eps) -> g_x ----------------
#define AN 32
__global__ void __launch_bounds__(256) attn_apply_kernel() {
    int bh = blockIdx.x;
    int b = bh / HEADSV, h = bh % HEADSV;
    int n0 = blockIdx.y * AN;
    int tid = threadIdx.x;
    __shared__ float skv[KV_CELLS];
    __shared__ float sq[AN][HD];
    __shared__ float so[AN][HD1];

    for (int c = tid; c < KV_CELLS; c += 256)
        skv[c] = g_kv[(size_t)bh * KV_CELLS + c];
    for (int idx = tid; idx < AN * HD; idx += 256) {
        int nl = idx / HD, d = idx % HD;
        sq[nl][d] = g_q[(size_t)(b * NSEQ + n0 + nl) * DIMV + h * HD + d];
    }
    __syncthreads();
    for (int t = tid; t < AN * HD1; t += 256) {
        int nl = t / HD1, e = t - nl * HD1;
        float s = 0.f;
#pragma unroll 8
        for (int d = 0; d < HD; d++)
            s = fmaf(sq[nl][d], skv[d * HD1 + e], s);
        so[nl][e] = s;
    }
    __syncthreads();
    for (int t = tid; t < AN * HD; t += 256) {
        int nl = t / HD, e = t - nl * HD;
        g_x[(size_t)(b * NSEQ + n0 + nl) * DIMV + h * HD + e] =
            so[nl][e] / (so[nl][HD1 - 1] + 1e-15f);
    }
}

// ---------------- depthwise conv (k=3, zero pad) + GLU ----------------
// float4 over channels (4 ch/thread) AND n-blocked (4 rows/thread) with a
// rolling window, so interior rows of g_y are read once instead of 3x.
#define NB 4
__global__ void __launch_bounds__(256) dwglu_kernel(
    const float* __restrict__ Wdw, const float* __restrict__ bdw)
{
    size_t idx = (size_t)blockIdx.x * 256 + threadIdx.x;
    size_t total = (size_t)MT / NB * (HIDV / 4);
    if (idx >= total) return;
    int c  = (int)(idx % (HIDV / 4)) * 4;      // first channel of group
    size_t rb = idx / (HIDV / 4);              // row-block index
    size_t row0 = rb * NB;                     // first row (b*NSEQ + n), NB | NSEQ
    int n0 = (int)(row0 & (NSEQ - 1));         // sequence pos of first row

    // weights/biases for x-branch (c..c+3) and gate-branch (c+HIDV..)
    float4 w0 = *(const float4*)(Wdw + c * 3);
    float4 w1 = *(const float4*)(Wdw + c * 3 + 4);
    float4 w2 = *(const float4*)(Wdw + c * 3 + 8);
    float4 bx = *(const float4*)(bdw + c);
    int cg = c + HIDV;
    float4 u0 = *(const float4*)(Wdw + cg * 3);
    float4 u1 = *(const float4*)(Wdw + cg * 3 + 4);
    float4 u2 = *(const float4*)(Wdw + cg * 3 + 8);
    float4 bg = *(const float4*)(bdw + cg);

    const float* bx0 = g_y + row0 * HID2;      // row pointer base
    const float4 z4 = make_float4(0.f, 0.f, 0.f, 0.f);

    // rolling window over rows n0-1 .. n0+NB
    float4 xm = (n0 > 0) ? *(const float4*)(bx0 - HID2 + c)  : z4;
    float4 gm = (n0 > 0) ? *(const float4*)(bx0 - HID2 + cg) : z4;
    float4 x0 = *(const float4*)(bx0 + c);
    float4 g0 = *(const float4*)(bx0 + cg);

#pragma unroll
    for (int nl = 0; nl < NB; nl++) {
        bool hp = (n0 + nl < NSEQ - 1);
        const float* bnext = bx0 + (size_t)(nl + 1) * HID2;
        float4 xp = hp ? *(const float4*)(bnext + c)  : z4;
        float4 gp = hp ? *(const float4*)(bnext + cg) : z4;

        float xg0 = fmaf(w0.x, xm.x, fmaf(w0.y, x0.x, fmaf(w0.z, xp.x, bx.x)));
        float xg1 = fmaf(w0.w, xm.y, fmaf(w1.x, x0.y, fmaf(w1.y, xp.y, bx.y)));
        float xg2 = fmaf(w1.z, xm.z, fmaf(w1.w, x0.z, fmaf(w2.x, xp.z, bx.z)));
        float xg3 = fmaf(w2.y, xm.w, fmaf(w2.z, x0.w, fmaf(w2.w, xp.w, bx.w)));

        float gg0 = fmaf(u0.x, gm.x, fmaf(u0.y, g0.x, fmaf(u0.z, gp.x, bg.x)));
        float gg1 = fmaf(u0.w, gm.y, fmaf(u1.x, g0.y, fmaf(u1.y, gp.y, bg.y)));
        float gg2 = fmaf(u1.z, gm.z, fmaf(u1.w, g0.z, fmaf(u2.x, gp.z, bg.z)));
        float gg3 = fmaf(u2.y, gm.w, fmaf(u2.z, g0.w, fmaf(u2.w, gp.w, bg.w)));

        float4 o;
        o.x = xg0 * (gg0 / (1.f + expf(-gg0)));
        o.y = xg1 * (gg1 / (1.f + expf(-gg1)));
        o.z = xg2 * (gg2 / (1.f + expf(-gg2)));
        o.w = xg3 * (gg3 / (1.f + expf(-gg3)));
        *(float4*)(g_y2 + (row0 + nl) * HIDV + c) = o;

        xm = x0; x0 = xp;
        gm = g0; g0 = gp;
    }
}

// ---------------- launch ----------------
extern "C" void kernel_launch(void* const* d_in, const int* in_sizes, int n_in,
                              void* d_out, int out_size)
{
    const float* hidden = (const float*)d_in[0];
    const float* temb   = (const float*)d_in[1];
    const float* sst    = (const float*)d_in[2];
    const float* Wq = (const float*)d_in[3];  const float* bq = (const float*)d_in[4];
    const float* Wk = (const float*)d_in[5];  const float* bk = (const float*)d_in[6];
    const float* Wv = (const float*)d_in[7];  const float* bv = (const float*)d_in[8];
    const float* Wo = (const float*)d_in[9];  const float* bo = (const float*)d_in[10];
    const float* W_inv = (const float*)d_in[11]; const float* b_inv = (const float*)d_in[12];
    const float* W_dw  = (const float*)d_in[13]; const float* b_dw  = (const float*)d_in[14];
    const float* W_pt  = (const float*)d_in[15];
    float* out = (float*)d_out;

    void *pm, *px, *pq, *pk, *pv, *ph2, *py, *py2;
    cudaGetSymbolAddress(&pm,  g_mods);
    cudaGetSymbolAddress(&px,  g_x);
    cudaGetSymbolAddress(&pq,  g_q);
    cudaGetSymbolAddress(&pk,  g_k);
    cudaGetSymbolAddress(&pv,  g_v);
    cudaGetSymbolAddress(&ph2, g_h2);
    cudaGetSymbolAddress(&py,  g_y);
    cudaGetSymbolAddress(&py2, g_y2);
    float* fm  = (float*)pm;  float* fx  = (float*)px;
    float* fq  = (float*)pq;  float* fk  = (float*)pk;  float* fv = (float*)pv;
    float* fh2 = (float*)ph2; float* fy  = (float*)py;  float* fy2 = (float*)py2;

    // 1. modulation vectors
    mods_kernel<<<(BBATCH * 6 * DIMV + 255) / 256, 256>>>(temb, sst);
    // 2. x = rms(hidden)*(1+scale_msa)+shift_msa
    rms_mod_kernel<<<MT, 256>>>(hidden, fx, 0, 1);
    // 3. fused QKV
    dim3 gQKV(3 * DIMV / 128, MT / 128);
    gemm_qkv_kernel<<<gQKV, 256>>>(fx, Wq, bq, Wk, bk, Wv, bv, fq, fk, fv);
    // 4. linear attention
    kv_partial_kernel<<<dim3(BBATCH * HEADSV, NCHUNK), 256>>>();
    kv_reduce_kernel<<<BBATCH * HEADSV, 256>>>();
    attn_apply_kernel<<<dim3(BBATCH * HEADSV, NSEQ / AN), 256>>>();   // writes g_x
    // 5. h2 = gate_msa*(attn @ Wo^T + bo) + hidden
    dim3 gD(DIMV / 128, MT / 128);
    gemm_kernel<0, 1><<<gD, 256>>>(fx, Wo, bo, fh2, DIMV, DIMV, hidden, fm, 2);
    // 6. y_in = rms(h2)*(1+scale_mlp)+shift_mlp
    rms_mod_kernel<<<MT, 256>>>(fh2, fx, 3, 4);
    // 7. y = silu(y_in @ W_inv^T + b_inv)
    dim3 gI(HID2 / 128, MT / 128);
    gemm_kernel<2, 0><<<gI, 256>>>(fx, W_inv, b_inv, fy, DIMV, HID2, nullptr, nullptr, 0);
    // 8. depthwise conv + GLU (4 channels x 4 rows per thread)
    size_t totb = (size_t)MT / NB * (HIDV / 4);
    dwglu_kernel<<<(unsigned)((totb + 255) / 256), 256>>>(W_dw, b_dw);
    // 9. out = h2 + gate_mlp * (y2 @ W_pt^T)
    gemm_kernel<0, 2><<<gD, 256>>>(fy2, W_pt, nullptr, out, HIDV, DIMV, fh2, fm, 5);
}

// round 17
// speedup vs baseline: 1.1159x; 1.1159x over previous
#include <cuda_runtime.h>
#include <math.h>
#include <stdint.h>

// ---------------- problem constants ----------------
#define DIMV   1152
#define HEADSV 16
#define HD     72
#define HD1    73
#define HIDV   4608
#define HID2   9216      // 2*HID
#define BBATCH 2
#define NSEQ   4096
#define MT     8192      // BBATCH*NSEQ
#define NCHUNK 16
#define KV_CELLS (HD*HD1)   // 5256
#define CPT    21           // ceil(5256/256)

// ---------------- scratch (device globals; no allocs) ----------------
__device__ float g_mods[BBATCH*6*DIMV];
__device__ float g_x  [(size_t)MT*DIMV];   // modulated input / reused as attn output
__device__ float g_q  [(size_t)MT*DIMV];
__device__ float g_k  [(size_t)MT*DIMV];
__device__ float g_v  [(size_t)MT*DIMV];
__device__ float g_kvp[(size_t)BBATCH*HEADSV*NCHUNK*KV_CELLS];
__device__ float g_kv [(size_t)BBATCH*HEADSV*KV_CELLS];
__device__ float g_h2 [(size_t)MT*DIMV];
__device__ float g_y  [(size_t)MT*HID2];
__device__ float g_y2 [(size_t)MT*HIDV];

// ---------------- small helpers ----------------
template<int ACT>
__device__ __forceinline__ float activate(float v) {
    if (ACT == 1) return fmaxf(v, 0.f);
    if (ACT == 2) return v / (1.f + expf(-v));
    return v;
}

__device__ __forceinline__ uint32_t f2tf32(float x) {
    uint32_t r;
    asm("cvt.rna.tf32.f32 %0, %1;" : "=r"(r) : "f"(x));
    return r;
}

// split x into tf32 hi + tf32 lo (lo = tf32(x - hi))
__device__ __forceinline__ void tf32_split(float x, uint32_t& hi, uint32_t& lo) {
    hi = f2tf32(x);
    float hif = __uint_as_float(hi);
    lo = f2tf32(x - hif);
}

__device__ __forceinline__ void mma_tf32(
    float& d0, float& d1, float& d2, float& d3,
    uint32_t a0, uint32_t a1, uint32_t a2, uint32_t a3,
    uint32_t b0, uint32_t b1)
{
    asm volatile(
        "mma.sync.aligned.m16n8k8.row.col.f32.tf32.tf32.f32 "
        "{%0,%1,%2,%3},{%4,%5,%6,%7},{%8,%9},{%0,%1,%2,%3};"
        : "+f"(d0), "+f"(d1), "+f"(d2), "+f"(d3)
        : "r"(a0), "r"(a1), "r"(a2), "r"(a3), "r"(b0), "r"(b1));
}

// ---------------- mods = scale_shift_table + temb ----------------
__global__ void mods_kernel(const float* __restrict__ temb,
                            const float* __restrict__ sst) {
    int i = blockIdx.x * 256 + threadIdx.x;
    if (i < BBATCH * 6 * DIMV)
        g_mods[i] = sst[i % (6 * DIMV)] + temb[i];
}

// ---------------- RMSNorm + adaLN modulation (float4) ----------------
__global__ void __launch_bounds__(256) rms_mod_kernel(
    const float* __restrict__ h, float* __restrict__ out,
    int shift_sel, int scale_sel)
{
    int row = blockIdx.x;              // 0..MT-1
    int b   = row >> 12;               // /NSEQ
    const float4* hr4 = (const float4*)(h + (size_t)row * DIMV);
    __shared__ float red[256];
    float s = 0.f;
    for (int i = threadIdx.x; i < DIMV / 4; i += 256) {
        float4 v = hr4[i];
        s += v.x * v.x + v.y * v.y + v.z * v.z + v.w * v.w;
    }
    red[threadIdx.x] = s;
    __syncthreads();
    for (int off = 128; off; off >>= 1) {
        if (threadIdx.x < off) red[threadIdx.x] += red[threadIdx.x + off];
        __syncthreads();
    }
    float inv = rsqrtf(red[0] / (float)DIMV + 1e-6f);
    const float4* sh4 = (const float4*)(g_mods + (b * 6 + shift_sel) * DIMV);
    const float4* sc4 = (const float4*)(g_mods + (b * 6 + scale_sel) * DIMV);
    float4* orow4 = (float4*)(out + (size_t)row * DIMV);
    for (int i = threadIdx.x; i < DIMV / 4; i += 256) {
        float4 v = hr4[i], sc = sc4[i], sh = sh4[i], o;
        o.x = v.x * inv * (1.f + sc.x) + sh.x;
        o.y = v.y * inv * (1.f + sc.y) + sh.y;
        o.z = v.z * inv * (1.f + sc.z) + sh.z;
        o.w = v.w * inv * (1.f + sc.w) + sh.w;
        orow4[i] = o;
    }
}

// ---------------- TF32-split tensor-core GEMM ----------------
// C = epi(A[M,K] @ W[Nt,K]^T), 3xTF32: D += Ahi*Bhi + Ahi*Blo + Alo*Bhi.
// Block 128x128, 8 warps (2M x 4N), warp tile 64x32, k-chunk 16.
// ACT: 0 none, 1 relu, 2 silu
// EPI: 0 act(acc+bias); 1 gate*(acc+bias)+resid; 2 resid+gate*acc
template<int ACT, int EPI>
__global__ void __launch_bounds__(256, 2) gemm_kernel(
    const float* __restrict__ A, const float* __restrict__ W,
    const float* __restrict__ bias, float* __restrict__ C,
    int K, int Nt,
    const float* __restrict__ resid, const float* __restrict__ gates,
    int gate_sel)
{
    __shared__ uint32_t Ah[128][17], Al[128][17];
    __shared__ uint32_t Bh[128][17], Bl[128][17];

    const int bm = blockIdx.y * 128;
    const int bn = blockIdx.x * 128;
    const int tid = threadIdx.x;
    const int lr = tid >> 2;             // 0..63 (row within tile half)
    const int lc = (tid & 3) << 2;       // k offset 0,4,8,12

    const int wid  = tid >> 5;           // 0..7
    const int lane = tid & 31;
    const int warpM = (wid & 1) * 64;    // 2 warps along M
    const int warpN = (wid >> 1) * 32;   // 4 warps along N
    const int g  = lane >> 2;            // group id 0..7
    const int t4 = lane & 3;             // thread in group

    const float* Ap = A + (size_t)(bm + lr) * K + lc;
    const float* Wp = W + (size_t)(bn + lr) * K + lc;
    const size_t str64 = (size_t)64 * K;

    float d[4][4][4];                    // [mt][nt][frag]
#pragma unroll
    for (int mt = 0; mt < 4; mt++)
#pragma unroll
        for (int nt = 0; nt < 4; nt++)
#pragma unroll
            for (int r = 0; r < 4; r++) d[mt][nt][r] = 0.f;

    // prologue: prefetch tile 0
    float4 pa0 = *(const float4*)(Ap);
    float4 pa1 = *(const float4*)(Ap + str64);
    float4 pb0 = *(const float4*)(Wp);
    float4 pb1 = *(const float4*)(Wp + str64);

    for (int k0 = 0; k0 < K; k0 += 16) {
        __syncthreads();   // previous compute finished reading smem
        {
            const float av0[4] = {pa0.x, pa0.y, pa0.z, pa0.w};
            const float av1[4] = {pa1.x, pa1.y, pa1.z, pa1.w};
            const float bv0[4] = {pb0.x, pb0.y, pb0.z, pb0.w};
            const float bv1[4] = {pb1.x, pb1.y, pb1.z, pb1.w};
#pragma unroll
            for (int j = 0; j < 4; j++) {
                uint32_t hi, lo;
                tf32_split(av0[j], hi, lo); Ah[lr][lc + j] = hi;      Al[lr][lc + j] = lo;
                tf32_split(av1[j], hi, lo); Ah[lr + 64][lc + j] = hi; Al[lr + 64][lc + j] = lo;
                tf32_split(bv0[j], hi, lo); Bh[lr][lc + j] = hi;      Bl[lr][lc + j] = lo;
                tf32_split(bv1[j], hi, lo); Bh[lr + 64][lc + j] = hi; Bl[lr + 64][lc + j] = lo;
            }
        }
        __syncthreads();

        // prefetch next chunk (overlaps with mma block)
        int kn = k0 + 16;
        if (kn < K) {
            pa0 = *(const float4*)(Ap + kn);
            pa1 = *(const float4*)(Ap + str64 + kn);
            pb0 = *(const float4*)(Wp + kn);
            pb1 = *(const float4*)(Wp + str64 + kn);
        }

#pragma unroll
        for (int ks = 0; ks < 2; ks++) {
            const int kb = ks * 8;
            // load B fragments for the 4 n-tiles
            uint32_t bh[4][2], bl[4][2];
#pragma unroll
            for (int nt = 0; nt < 4; nt++) {
                int n = warpN + nt * 8 + g;
                bh[nt][0] = Bh[n][kb + t4];     bh[nt][1] = Bh[n][kb + t4 + 4];
                bl[nt][0] = Bl[n][kb + t4];     bl[nt][1] = Bl[n][kb + t4 + 4];
            }
#pragma unroll
            for (int mt = 0; mt < 4; mt++) {
                int r0 = warpM + mt * 16 + g;
                uint32_t ah0 = Ah[r0][kb + t4],     ah1 = Ah[r0 + 8][kb + t4];
                uint32_t ah2 = Ah[r0][kb + t4 + 4], ah3 = Ah[r0 + 8][kb + t4 + 4];
                uint32_t al0 = Al[r0][kb + t4],     al1 = Al[r0 + 8][kb + t4];
                uint32_t al2 = Al[r0][kb + t4 + 4], al3 = Al[r0 + 8][kb + t4 + 4];
#pragma unroll
                for (int nt = 0; nt < 4; nt++) {
                    mma_tf32(d[mt][nt][0], d[mt][nt][1], d[mt][nt][2], d[mt][nt][3],
                             ah0, ah1, ah2, ah3, bh[nt][0], bh[nt][1]);
                    mma_tf32(d[mt][nt][0], d[mt][nt][1], d[mt][nt][2], d[mt][nt][3],
                             ah0, ah1, ah2, ah3, bl[nt][0], bl[nt][1]);
                    mma_tf32(d[mt][nt][0], d[mt][nt][1], d[mt][nt][2], d[mt][nt][3],
                             al0, al1, al2, al3, bh[nt][0], bh[nt][1]);
                }
            }
        }
    }

    // ---------------- epilogue ----------------
#pragma unroll
    for (int mt = 0; mt < 4; mt++) {
        int rowA = bm + warpM + mt * 16 + g;     // rows rowA and rowA+8
#pragma unroll
        for (int half = 0; half < 2; half++) {
            int row = rowA + half * 8;
            int bidx = row >> 12;                // row / NSEQ
            float* crow = C + (size_t)row * Nt;
            const float* grow = (EPI != 0) ? (gates + (bidx * 6 + gate_sel) * DIMV) : (const float*)0;
            const float* rrow = (EPI != 0) ? (resid + (size_t)row * Nt) : (const float*)0;
#pragma unroll
            for (int nt = 0; nt < 4; nt++) {
                int col = bn + warpN + nt * 8 + t4 * 2;
                float vx = d[mt][nt][half * 2 + 0];
                float vy = d[mt][nt][half * 2 + 1];
                if (EPI == 0) {
                    if (bias) {
                        float2 bv = *(const float2*)(bias + col);
                        vx += bv.x; vy += bv.y;
                    }
                    vx = activate<ACT>(vx); vy = activate<ACT>(vy);
                } else if (EPI == 1) {
                    float2 bv = *(const float2*)(bias + col);
                    float2 gv = *(const float2*)(grow + col);
                    float2 rv = *(const float2*)(rrow + col);
                    vx = gv.x * (vx + bv.x) + rv.x;
                    vy = gv.y * (vy + bv.y) + rv.y;
                } else {
                    float2 gv = *(const float2*)(grow + col);
                    float2 rv = *(const float2*)(rrow + col);
                    vx = rv.x + gv.x * vx;
                    vy = rv.y + gv.y * vy;
                }
                *(float2*)(crow + col) = make_float2(vx, vy);
            }
        }
    }
}

// ---------------- linear attention: partial kv = sum_n k ⊗ [v;1] ----------------
__global__ void __launch_bounds__(256) kv_partial_kernel() {
    int bh    = blockIdx.x;              // 0..B*H-1
    int chunk = blockIdx.y;              // 0..NCHUNK-1
    int b = bh / HEADSV, h = bh % HEADSV;
    int n0 = chunk * (NSEQ / NCHUNK);    // 256 rows per chunk
    __shared__ float sk[16][HD];
    __shared__ float sv[16][HD1];
    int tid = threadIdx.x;
    float acc[CPT];
#pragma unroll
    for (int i = 0; i < CPT; i++) acc[i] = 0.f;

    const int d0 = tid / HD1;
    const int e0 = tid - d0 * HD1;

    for (int nt = 0; nt < NSEQ / NCHUNK; nt += 16) {
        __syncthreads();
        for (int idx = tid; idx < 16 * HD; idx += 256) {
            int ns = idx / HD, d = idx % HD;
            size_t r = (size_t)(b * NSEQ + n0 + nt + ns) * DIMV + h * HD + d;
            sk[ns][d] = g_k[r];
            sv[ns][d] = g_v[r];
        }
        if (tid < 16) sv[tid][HD] = 1.0f;
        __syncthreads();
        int d = d0, e = e0, c = tid;
#pragma unroll
        for (int i = 0; i < CPT; i++) {
            if (c < KV_CELLS) {
#pragma unroll
                for (int ns = 0; ns < 16; ns++)
                    acc[i] = fmaf(sk[ns][d], sv[ns][e], acc[i]);
            }
            c += 256; d += 3; e += 37;
            if (e >= HD1) { e -= HD1; d += 1; }
        }
    }
    float* outp = g_kvp + ((size_t)bh * NCHUNK + chunk) * KV_CELLS;
#pragma unroll
    for (int i = 0; i < CPT; i++) {
        int c = tid + i * 256;
        if (c < KV_CELLS) outp[c] = acc[i];
    }
}

__global__ void kv_reduce_kernel() {
    int bh = blockIdx.x;
    for (int c = threadIdx.x; c < KV_CELLS; c += 256) {
        float s = 0.f;
        for (int j = 0; j < NCHUNK; j++)
            s += g_kvp[((size_t)bh * NCHUNK + j) * KV_CELLS + c];
        g_kv[(size_t)bh * KV_CELLS + c] = s;
    }
}

// ---------------- out = (q @ kv)[:72] / ((q @ kv)[72]+eps) -> g_x ----------------
#define AN 32
__global__ void __launch_bounds__(256) attn_apply_kernel() {
    int bh = blockIdx.x;
    int b = bh / HEADSV, h = bh % HEADSV;
    int n0 = blockIdx.y * AN;
    int tid = threadIdx.x;
    __shared__ float skv[KV_CELLS];
    __shared__ float sq[AN][HD];
    __shared__ float so[AN][HD1];

    for (int c = tid; c < KV_CELLS; c += 256)
        skv[c] = g_kv[(size_t)bh * KV_CELLS + c];
    for (int idx = tid; idx < AN * HD; idx += 256) {
        int nl = idx / HD, d = idx % HD;
        sq[nl][d] = g_q[(size_t)(b * NSEQ + n0 + nl) * DIMV + h * HD + d];
    }
    __syncthreads();
    for (int t = tid; t < AN * HD1; t += 256) {
        int nl = t / HD1, e = t - nl * HD1;
        float s = 0.f;
#pragma unroll 8
        for (int d = 0; d < HD; d++)
            s = fmaf(sq[nl][d], skv[d * HD1 + e], s);
        so[nl][e] = s;
    }
    __syncthreads();
    for (int t = tid; t < AN * HD; t += 256) {
        int nl = t / HD, e = t - nl * HD;
        g_x[(size_t)(b * NSEQ + n0 + nl) * DIMV + h * HD + e] =
            so[nl][e] / (so[nl][HD1 - 1] + 1e-15f);
    }
}

// ---------------- depthwise conv (k=3, zero pad) + GLU ----------------
// float4 over channels (4 ch/thread) AND n-blocked (4 rows/thread) with a
// rolling window, so interior rows of g_y are read once instead of 3x.
#define NB 4
__global__ void __launch_bounds__(256) dwglu_kernel(
    const float* __restrict__ Wdw, const float* __restrict__ bdw)
{
    size_t idx = (size_t)blockIdx.x * 256 + threadIdx.x;
    size_t total = (size_t)MT / NB * (HIDV / 4);
    if (idx >= total) return;
    int c  = (int)(idx % (HIDV / 4)) * 4;      // first channel of group
    size_t rb = idx / (HIDV / 4);              // row-block index
    size_t row0 = rb * NB;                     // first row (b*NSEQ + n), NB | NSEQ
    int n0 = (int)(row0 & (NSEQ - 1));         // sequence pos of first row

    float4 w0 = *(const float4*)(Wdw + c * 3);
    float4 w1 = *(const float4*)(Wdw + c * 3 + 4);
    float4 w2 = *(const float4*)(Wdw + c * 3 + 8);
    float4 bx = *(const float4*)(bdw + c);
    int cg = c + HIDV;
    float4 u0 = *(const float4*)(Wdw + cg * 3);
    float4 u1 = *(const float4*)(Wdw + cg * 3 + 4);
    float4 u2 = *(const float4*)(Wdw + cg * 3 + 8);
    float4 bg = *(const float4*)(bdw + cg);

    const float* bx0 = g_y + row0 * HID2;
    const float4 z4 = make_float4(0.f, 0.f, 0.f, 0.f);

    float4 xm = (n0 > 0) ? *(const float4*)(bx0 - HID2 + c)  : z4;
    float4 gm = (n0 > 0) ? *(const float4*)(bx0 - HID2 + cg) : z4;
    float4 x0 = *(const float4*)(bx0 + c);
    float4 g0 = *(const float4*)(bx0 + cg);

#pragma unroll
    for (int nl = 0; nl < NB; nl++) {
        bool hp = (n0 + nl < NSEQ - 1);
        const float* bnext = bx0 + (size_t)(nl + 1) * HID2;
        float4 xp = hp ? *(const float4*)(bnext + c)  : z4;
        float4 gp = hp ? *(const float4*)(bnext + cg) : z4;

        float xg0 = fmaf(w0.x, xm.x, fmaf(w0.y, x0.x, fmaf(w0.z, xp.x, bx.x)));
        float xg1 = fmaf(w0.w, xm.y, fmaf(w1.x, x0.y, fmaf(w1.y, xp.y, bx.y)));
        float xg2 = fmaf(w1.z, xm.z, fmaf(w1.w, x0.z, fmaf(w2.x, xp.z, bx.z)));
        float xg3 = fmaf(w2.y, xm.w, fmaf(w2.z, x0.w, fmaf(w2.w, xp.w, bx.w)));

        float gg0 = fmaf(u0.x, gm.x, fmaf(u0.y, g0.x, fmaf(u0.z, gp.x, bg.x)));
        float gg1 = fmaf(u0.w, gm.y, fmaf(u1.x, g0.y, fmaf(u1.y, gp.y, bg.y)));
        float gg2 = fmaf(u1.z, gm.z, fmaf(u1.w, g0.z, fmaf(u2.x, gp.z, bg.z)));
        float gg3 = fmaf(u2.y, gm.w, fmaf(u2.z, g0.w, fmaf(u2.w, gp.w, bg.w)));

        float4 o;
        o.x = xg0 * (gg0 / (1.f + expf(-gg0)));
        o.y = xg1 * (gg1 / (1.f + expf(-gg1)));
        o.z = xg2 * (gg2 / (1.f + expf(-gg2)));
        o.w = xg3 * (gg3 / (1.f + expf(-gg3)));
        *(float4*)(g_y2 + (row0 + nl) * HIDV + c) = o;

        xm = x0; x0 = xp;
        gm = g0; g0 = gp;
    }
}

// ---------------- launch ----------------
extern "C" void kernel_launch(void* const* d_in, const int* in_sizes, int n_in,
                              void* d_out, int out_size)
{
    const float* hidden = (const float*)d_in[0];
    const float* temb   = (const float*)d_in[1];
    const float* sst    = (const float*)d_in[2];
    const float* Wq = (const float*)d_in[3];  const float* bq = (const float*)d_in[4];
    const float* Wk = (const float*)d_in[5];  const float* bk = (const float*)d_in[6];
    const float* Wv = (const float*)d_in[7];  const float* bv = (const float*)d_in[8];
    const float* Wo = (const float*)d_in[9];  const float* bo = (const float*)d_in[10];
    const float* W_inv = (const float*)d_in[11]; const float* b_inv = (const float*)d_in[12];
    const float* W_dw  = (const float*)d_in[13]; const float* b_dw  = (const float*)d_in[14];
    const float* W_pt  = (const float*)d_in[15];
    float* out = (float*)d_out;

    void *pm, *px, *pq, *pk, *pv, *ph2, *py, *py2;
    cudaGetSymbolAddress(&pm,  g_mods);
    cudaGetSymbolAddress(&px,  g_x);
    cudaGetSymbolAddress(&pq,  g_q);
    cudaGetSymbolAddress(&pk,  g_k);
    cudaGetSymbolAddress(&pv,  g_v);
    cudaGetSymbolAddress(&ph2, g_h2);
    cudaGetSymbolAddress(&py,  g_y);
    cudaGetSymbolAddress(&py2, g_y2);
    float* fm  = (float*)pm;  float* fx  = (float*)px;
    float* fq  = (float*)pq;  float* fk  = (float*)pk;  float* fv = (float*)pv;
    float* fh2 = (float*)ph2; float* fy  = (float*)py;  float* fy2 = (float*)py2;

    // 1. modulation vectors
    mods_kernel<<<(BBATCH * 6 * DIMV + 255) / 256, 256>>>(temb, sst);
    // 2. x = rms(hidden)*(1+scale_msa)+shift_msa
    rms_mod_kernel<<<MT, 256>>>(hidden, fx, 0, 1);
    // 3. QKV (tf32 tensor-core GEMMs)
    dim3 gD(DIMV / 128, MT / 128);
    gemm_kernel<1, 0><<<gD, 256>>>(fx, Wq, bq, fq, DIMV, DIMV, nullptr, nullptr, 0);
    gemm_kernel<1, 0><<<gD, 256>>>(fx, Wk, bk, fk, DIMV, DIMV, nullptr, nullptr, 0);
    gemm_kernel<0, 0><<<gD, 256>>>(fx, Wv, bv, fv, DIMV, DIMV, nullptr, nullptr, 0);
    // 4. linear attention
    kv_partial_kernel<<<dim3(BBATCH * HEADSV, NCHUNK), 256>>>();
    kv_reduce_kernel<<<BBATCH * HEADSV, 256>>>();
    attn_apply_kernel<<<dim3(BBATCH * HEADSV, NSEQ / AN), 256>>>();   // writes g_x
    // 5. h2 = gate_msa*(attn @ Wo^T + bo) + hidden
    gemm_kernel<0, 1><<<gD, 256>>>(fx, Wo, bo, fh2, DIMV, DIMV, hidden, fm, 2);
    // 6. y_in = rms(h2)*(1+scale_mlp)+shift_mlp
    rms_mod_kernel<<<MT, 256>>>(fh2, fx, 3, 4);
    // 7. y = silu(y_in @ W_inv^T + b_inv)
    dim3 gI(HID2 / 128, MT / 128);
    gemm_kernel<2, 0><<<gI, 256>>>(fx, W_inv, b_inv, fy, DIMV, HID2, nullptr, nullptr, 0);
    // 8. depthwise conv + GLU (4 channels x 4 rows per thread)
    size_t totb = (size_t)MT / NB * (HIDV / 4);
    dwglu_kernel<<<(unsigned)((totb + 255) / 256), 256>>>(W_dw, b_dw);
    // 9. out = h2 + gate_mlp * (y2 @ W_pt^T)
    gemm_kernel<0, 2><<<gD, 256>>>(fy2, W_pt, nullptr, out, HIDV, DIMV, fh2, fm, 5);
}